// round 5
// baseline (speedup 1.0000x reference)
#include <cuda_runtime.h>
#include <cstdint>

// Problem constants
#define Bb 64
#define Cc 64
#define Tt 128
#define Vv 25
#define Rr 8
#define TSs 9
#define OUTo 64

typedef unsigned long long ull;

// Scratch (device globals — no allocation allowed)
__device__ float g_xbar[Bb * Cc * Vv];          // (b,c,v) mean over t
__device__ float g_rel[Bb * Rr * Vv * Vv];      // (b,r,i,j)
__device__ float g_z[Bb * Cc * Tt * Vv];        // (b,c,t,v) intermediate

// ---------- packed f32x2 helpers (sm_103a FFMA2 path) ----------
__device__ __forceinline__ void ffma2(ull& acc, ull a, ull b) {
    asm("fma.rn.f32x2 %0, %1, %2, %0;" : "+l"(acc) : "l"(a), "l"(b));
}
__device__ __forceinline__ ull splat2(float x) {
    ull r;
    unsigned int xu = __float_as_uint(x);
    asm("mov.b64 %0, {%1, %1};" : "=l"(r) : "r"(xu));
    return r;
}
__device__ __forceinline__ float2 lo_hi(ull v) {
    float2 f;
    asm("mov.b64 {%0, %1}, %2;" : "=f"(f.x), "=f"(f.y) : "l"(v));
    return f;
}
__device__ __forceinline__ void cp_async16(float* smem_dst, const float* gmem_src) {
    unsigned s = (unsigned)__cvta_generic_to_shared(smem_dst);
    asm volatile("cp.async.cg.shared.global [%0], [%1], 16;\n" :: "r"(s), "l"(gmem_src));
}

// ============================================================
// K1: xbar[b,c,v] = mean_t x[b,c,t,v].  grid = B*C, block = 128
// ============================================================
__global__ void k1_xbar(const float* __restrict__ x) {
    __shared__ __align__(16) float xs[Tt * Vv];
    __shared__ float part[5][Vv];
    int bc = blockIdx.x, tid = threadIdx.x;
    const float4* xg4 = reinterpret_cast<const float4*>(x + (size_t)bc * (Tt * Vv));
    float4* xs4 = reinterpret_cast<float4*>(xs);
    for (int f = tid; f < Tt * Vv / 4; f += 128) xs4[f] = xg4[f];
    __syncthreads();
    if (tid < 125) {
        int v = tid % 25, s = tid / 25;
        int t0 = s * 26;
        int t1 = t0 + 26; if (t1 > Tt) t1 = Tt;
        float acc = 0.f;
        for (int t = t0; t < t1; t++) acc += xs[t * Vv + v];
        part[s][v] = acc;
    }
    __syncthreads();
    if (tid < Vv) {
        float acc = part[0][tid] + part[1][tid] + part[2][tid] + part[3][tid] + part[4][tid];
        g_xbar[bc * Vv + tid] = acc * (1.f / (float)Tt);
    }
}

// ============================================================
// K2: rel[b,r,i,j] = tanh(x1[b,r,i] - x2[b,r,j]).  grid = B, block = 256
// ============================================================
__global__ void k2_rel(const float* __restrict__ W1, const float* __restrict__ b1,
                       const float* __restrict__ W2, const float* __restrict__ b2) {
    __shared__ float xb[Cc * Vv];
    __shared__ float w1s[Rr * Cc], w2s[Rr * Cc];
    __shared__ float x1s[Rr * Vv], x2s[Rr * Vv];
    __shared__ float b1s[Rr], b2s[Rr];
    int b = blockIdx.x, tid = threadIdx.x;
    for (int idx = tid; idx < Cc * Vv; idx += 256) xb[idx] = g_xbar[b * (Cc * Vv) + idx];
    for (int idx = tid; idx < Rr * Cc; idx += 256) { w1s[idx] = W1[idx]; w2s[idx] = W2[idx]; }
    if (tid < Rr) { b1s[tid] = b1[tid]; b2s[tid] = b2[tid]; }
    __syncthreads();
    if (tid < Rr * Vv) {
        int r = tid / Vv, v = tid % Vv;
        float a1 = b1s[r], a2 = b2s[r];
        #pragma unroll 8
        for (int c = 0; c < Cc; c++) {
            float xv = xb[c * Vv + v];
            a1 = fmaf(w1s[r * Cc + c], xv, a1);
            a2 = fmaf(w2s[r * Cc + c], xv, a2);
        }
        x1s[tid] = a1; x2s[tid] = a2;
    }
    __syncthreads();
    for (int idx = tid; idx < Rr * Vv * Vv; idx += 256) {
        int r = idx / (Vv * Vv), rem = idx % (Vv * Vv);
        int i = rem / Vv, j = rem % Vv;
        g_rel[b * (Rr * Vv * Vv) + idx] = tanhf(x1s[r * Vv + i] - x2s[r * Vv + j]);
    }
}

// ============================================================
// K3: per (b,c) block, 128 threads = 16 t-octs x 8 i-chunks.
//   Adyn_k[v][i] = sum_r W4[(c*9+k),r]*rel[b,r,v,i] + b4[c*9+k] + A[v,i]
//   z[t][i]      = sum_{k,v} xpad[t+k][v] * Adyn_k[v][i]
// Thread: q = tid&7 owns i in [4q, 4q+4) (one ulonglong2);
//         oct = tid>>3 owns t in [8*oct, 8*oct+8).
// Per (k,v): ONE broadcast LDS.128 feeds 16 FFMA2.
// smem: Akp 28.8KB + xs 14.4KB + misc < 44KB (static, <48KB OK).
// ============================================================
#define IPAD 32                  // i padded 25 -> 32 (8 ulonglong2 per row)
#define AKP_SZ (TSs * Vv * IPAD) // 7200
#define RL 144                   // x row length in [v][t] layout (mult of 4)
#define XS_SZ (Vv * RL)          // 3600

__global__ __launch_bounds__(128) void k3_z(const float* __restrict__ x,
                                            const float* __restrict__ A,
                                            const float* __restrict__ W4,
                                            const float* __restrict__ b4) {
    __shared__ __align__(16) float Akp[AKP_SZ];
    __shared__ __align__(16) float xs[XS_SZ];
    __shared__ float w4s[TSs * Rr];
    __shared__ float b4s[TSs];

    int bc = blockIdx.x;
    int b = bc >> 6, c = bc & 63;
    int tid = threadIdx.x;

    if (tid < TSs * Rr) w4s[tid] = W4[c * (TSs * Rr) + tid];
    if (tid < TSs) b4s[tid] = b4[c * TSs + tid];
    __syncthreads();

    // ---- build Adyn from global rel/A (coalesced, mostly L2-resident) ----
    const float* relg = g_rel + b * (Rr * Vv * Vv);
    for (int vi = tid; vi < Vv * Vv; vi += 128) {
        float r8[Rr];
        #pragma unroll
        for (int r = 0; r < Rr; r++) r8[r] = __ldg(&relg[r * (Vv * Vv) + vi]);
        float av = __ldg(&A[vi]);
        int v = vi / Vv, i = vi - v * Vv;
        #pragma unroll
        for (int k = 0; k < TSs; k++) {
            float acc = b4s[k] + av;
            #pragma unroll
            for (int r = 0; r < Rr; r++) acc = fmaf(w4s[k * Rr + r], r8[r], acc);
            Akp[(k * Vv + v) * IPAD + i] = acc;
        }
    }
    // zero i-padding [25,32) in all 225 rows
    for (int idx = tid; idx < TSs * Vv * 7; idx += 128) {
        int row = idx / 7, j = idx - row * 7;
        Akp[row * IPAD + Vv + j] = 0.f;
    }
    // ---- causal-padded x tile, transposed to [v][t] ----
    const float* xg = x + (size_t)bc * (Tt * Vv);
    for (int idx = tid; idx < XS_SZ; idx += 128) {
        int v = idx / RL, t = idx - v * RL;
        xs[idx] = (t >= (TSs - 1) && t < Tt + TSs - 1) ? xg[(t - (TSs - 1)) * Vv + v] : 0.f;
    }
    __syncthreads();

    // ---- main compute ----
    int q = tid & 7, oct = tid >> 3;
    int t0 = oct * 8;
    ull acc0[8], acc1[8];          // [dt]: acc0 = i(4q,4q+1), acc1 = i(4q+2,4q+3)
    #pragma unroll
    for (int dt = 0; dt < 8; dt++) { acc0[dt] = 0ull; acc1[dt] = 0ull; }

    #pragma unroll 1
    for (int v = 0; v < Vv; v++) {
        const float4* xr = reinterpret_cast<const float4*>(&xs[v * RL + t0]);
        float4 xa = xr[0], xb = xr[1], xc = xr[2], xd = xr[3];
        float tap[16] = {xa.x, xa.y, xa.z, xa.w, xb.x, xb.y, xb.z, xb.w,
                         xc.x, xc.y, xc.z, xc.w, xd.x, xd.y, xd.z, xd.w};
        ull ring[8];
        #pragma unroll
        for (int j = 0; j < 8; j++) ring[j] = splat2(tap[j]);
        #pragma unroll
        for (int k = 0; k < TSs; k++) {
            ulonglong2 A2 = *reinterpret_cast<const ulonglong2*>(
                &Akp[(k * Vv + v) * IPAD + 4 * q]);
            #pragma unroll
            for (int dt = 0; dt < 8; dt++) {
                ull s = ring[(k + dt) & 7];
                ffma2(acc0[dt], A2.x, s);
                ffma2(acc1[dt], A2.y, s);
            }
            if (k < 8) ring[k & 7] = splat2(tap[k + 8]);
        }
    }
    __syncthreads();               // everyone done reading xs

    // ---- stage z (alias xs) for coalesced global store ----
    float* zst = xs;
    int i0 = 4 * q;
    #pragma unroll
    for (int dt = 0; dt < 8; dt++) {
        int t = t0 + dt;
        float2 f0 = lo_hi(acc0[dt]);
        float2 f1 = lo_hi(acc1[dt]);
        if (i0 < Vv)     zst[t * Vv + i0]     = f0.x;
        if (i0 + 1 < Vv) zst[t * Vv + i0 + 1] = f0.y;
        if (i0 + 2 < Vv) zst[t * Vv + i0 + 2] = f1.x;
        if (i0 + 3 < Vv) zst[t * Vv + i0 + 3] = f1.y;
    }
    __syncthreads();
    float4* zg4 = reinterpret_cast<float4*>(g_z + (size_t)bc * (Tt * Vv));
    const float4* zs4 = reinterpret_cast<const float4*>(zst);
    for (int f = tid; f < Tt * Vv / 4; f += 128) zg4[f] = zs4[f];
}

// ============================================================
// K4: out[b,o,n] = b3[o] + sum_c W3[o,c] * z[b,c,n]
// grid = (25 n-tiles of 128, B), block = 256 (8 warps).
// c streamed in 4 chunks of 16, double-buffered via cp.async so the
// gmem z reads overlap FFMA2 compute.
// o warp-uniform (o0 = warp*8): w LDS.128s are broadcasts.
// n0 = lane*4: z LDS.128 coalesced conflict-free.
// ============================================================
#define CCH 16
__global__ __launch_bounds__(256) void k4_conv3(const float* __restrict__ W3,
                                                const float* __restrict__ b3,
                                                float* __restrict__ out) {
    __shared__ __align__(16) float w3t[Cc * OUTo];       // [c][o] 16KB
    __shared__ __align__(16) float zs[2][CCH * 128];     // 2 x 8KB
    int nt = blockIdx.x, b = blockIdx.y;
    int tid = threadIdx.x;

    for (int idx = tid; idx < OUTo * Cc; idx += 256) {
        int o = idx >> 6, c = idx & 63;
        w3t[c * OUTo + o] = W3[idx];
    }

    const float* zbase = g_z + (size_t)b * (Cc * Tt * Vv) + nt * 128;
    // issue chunk ci into buffer buf: CCH rows x 128 floats = 512 float4
    auto issue = [&](int ci, int buf) {
        #pragma unroll
        for (int rep = 0; rep < 2; rep++) {
            int f = tid + rep * 256;
            int row = f >> 5, seg = f & 31;
            cp_async16(&zs[buf][row * 128 + seg * 4],
                       zbase + (size_t)(ci * CCH + row) * (Tt * Vv) + seg * 4);
        }
        asm volatile("cp.async.commit_group;\n" ::: "memory");
    };

    issue(0, 0);

    int w = tid >> 5, lane = tid & 31;
    int o0 = w * 8, n0 = lane * 4;

    ull acc[4][4];     // [o-pair][n]
    #pragma unroll
    for (int p = 0; p < 4; p++)
        #pragma unroll
        for (int qq = 0; qq < 4; qq++) acc[p][qq] = 0ull;

    #pragma unroll 1
    for (int ci = 0; ci < Cc / CCH; ci++) {
        if (ci < Cc / CCH - 1) issue(ci + 1, (ci + 1) & 1);
        if (ci < Cc / CCH - 1) { asm volatile("cp.async.wait_group 1;\n" ::: "memory"); }
        else                   { asm volatile("cp.async.wait_group 0;\n" ::: "memory"); }
        __syncthreads();       // chunk ci visible to all threads (also covers w3t on ci=0)
        const float* zb = zs[ci & 1];
        #pragma unroll 4
        for (int cl = 0; cl < CCH; cl++) {
            int c = ci * CCH + cl;
            const ulonglong2* wp =
                reinterpret_cast<const ulonglong2*>(&w3t[c * OUTo + o0]);
            ulonglong2 wa = wp[0];   // warp-uniform broadcast
            ulonglong2 wb = wp[1];
            float4 z4 = *reinterpret_cast<const float4*>(&zb[cl * 128 + n0]);
            ull zs0 = splat2(z4.x), zs1 = splat2(z4.y);
            ull zs2 = splat2(z4.z), zs3 = splat2(z4.w);
            ffma2(acc[0][0], wa.x, zs0); ffma2(acc[0][1], wa.x, zs1);
            ffma2(acc[0][2], wa.x, zs2); ffma2(acc[0][3], wa.x, zs3);
            ffma2(acc[1][0], wa.y, zs0); ffma2(acc[1][1], wa.y, zs1);
            ffma2(acc[1][2], wa.y, zs2); ffma2(acc[1][3], wa.y, zs3);
            ffma2(acc[2][0], wb.x, zs0); ffma2(acc[2][1], wb.x, zs1);
            ffma2(acc[2][2], wb.x, zs2); ffma2(acc[2][3], wb.x, zs3);
            ffma2(acc[3][0], wb.y, zs0); ffma2(acc[3][1], wb.y, zs1);
            ffma2(acc[3][2], wb.y, zs2); ffma2(acc[3][3], wb.y, zs3);
        }
        __syncthreads();       // done reading buffer before it is refilled
    }

    float* ob = out + (size_t)b * OUTo * (Tt * Vv) + nt * 128 + n0;
    #pragma unroll
    for (int p = 0; p < 4; p++) {
        int oA = o0 + 2 * p, oB = oA + 1;
        float bA = __ldg(&b3[oA]), bB = __ldg(&b3[oB]);
        float2 f0 = lo_hi(acc[p][0]), f1 = lo_hi(acc[p][1]);
        float2 f2 = lo_hi(acc[p][2]), f3 = lo_hi(acc[p][3]);
        float4 vA = make_float4(f0.x + bA, f1.x + bA, f2.x + bA, f3.x + bA);
        float4 vB = make_float4(f0.y + bB, f1.y + bB, f2.y + bB, f3.y + bB);
        *reinterpret_cast<float4*>(ob + (size_t)oA * (Tt * Vv)) = vA;
        *reinterpret_cast<float4*>(ob + (size_t)oB * (Tt * Vv)) = vB;
    }
}

// ============================================================
extern "C" void kernel_launch(void* const* d_in, const int* in_sizes, int n_in,
                              void* d_out, int out_size) {
    const float* x  = (const float*)d_in[0];
    const float* A  = (const float*)d_in[1];
    const float* W1 = (const float*)d_in[2];
    const float* b1 = (const float*)d_in[3];
    const float* W2 = (const float*)d_in[4];
    const float* b2 = (const float*)d_in[5];
    const float* W4 = (const float*)d_in[6];
    const float* b4 = (const float*)d_in[7];
    const float* W3 = (const float*)d_in[8];
    const float* b3 = (const float*)d_in[9];
    float* out = (float*)d_out;

    k1_xbar<<<Bb * Cc, 128>>>(x);
    k2_rel<<<Bb, 256>>>(W1, b1, W2, b2);
    k3_z<<<Bb * Cc, 128>>>(x, A, W4, b4);
    k4_conv3<<<dim3(25, Bb), 256>>>(W3, b3, out);
}

// round 6
// speedup vs baseline: 1.3892x; 1.3892x over previous
#include <cuda_runtime.h>
#include <cstdint>

// Problem constants
#define Bb 64
#define Cc 64
#define Tt 128
#define Vv 25
#define Rr 8
#define TSs 9
#define OUTo 64

typedef unsigned long long ull;

// Scratch (device globals — no allocation allowed)
__device__ float g_xbar[Bb * Cc * Vv];          // (b,c,v) mean over t
__device__ float g_rel[Bb * Rr * Vv * Vv];      // (b,r,i,j)
__device__ float g_z[Bb * Cc * Tt * Vv];        // (b,c,t,v) intermediate

// ---------- packed f32x2 helpers ----------
__device__ __forceinline__ void ffma2(ull& acc, ull a, ull b) {
    asm("fma.rn.f32x2 %0, %1, %2, %0;" : "+l"(acc) : "l"(a), "l"(b));
}
__device__ __forceinline__ ull splat2(float x) {
    ull r;
    unsigned int xu = __float_as_uint(x);
    asm("mov.b64 %0, {%1, %1};" : "=l"(r) : "r"(xu));
    return r;
}
__device__ __forceinline__ float2 lo_hi(ull v) {
    float2 f;
    asm("mov.b64 {%0, %1}, %2;" : "=f"(f.x), "=f"(f.y) : "l"(v));
    return f;
}
__device__ __forceinline__ void cp_async16(float* smem_dst, const float* gmem_src) {
    unsigned s = (unsigned)__cvta_generic_to_shared(smem_dst);
    asm volatile("cp.async.cg.shared.global [%0], [%1], 16;\n" :: "r"(s), "l"(gmem_src));
}
__device__ __forceinline__ float to_tf32(float x) {
    unsigned u;
    asm("cvt.rna.tf32.f32 %0, %1;" : "=r"(u) : "f"(x));
    return __uint_as_float(u);
}
__device__ __forceinline__ void mma_tf32(float* c, const unsigned* a, const unsigned* b) {
    asm volatile(
        "mma.sync.aligned.m16n8k8.row.col.f32.tf32.tf32.f32 "
        "{%0,%1,%2,%3}, {%4,%5,%6,%7}, {%8,%9}, {%0,%1,%2,%3};"
        : "+f"(c[0]), "+f"(c[1]), "+f"(c[2]), "+f"(c[3])
        : "r"(a[0]), "r"(a[1]), "r"(a[2]), "r"(a[3]), "r"(b[0]), "r"(b[1]));
}

// ============================================================
// K1: xbar[b,c,v] = mean_t x[b,c,t,v].  grid = B*C, block = 128
// ============================================================
__global__ void k1_xbar(const float* __restrict__ x) {
    __shared__ __align__(16) float xs[Tt * Vv];
    __shared__ float part[5][Vv];
    int bc = blockIdx.x, tid = threadIdx.x;
    const float4* xg4 = reinterpret_cast<const float4*>(x + (size_t)bc * (Tt * Vv));
    float4* xs4 = reinterpret_cast<float4*>(xs);
    for (int f = tid; f < Tt * Vv / 4; f += 128) xs4[f] = xg4[f];
    __syncthreads();
    if (tid < 125) {
        int v = tid % 25, s = tid / 25;
        int t0 = s * 26;
        int t1 = t0 + 26; if (t1 > Tt) t1 = Tt;
        float acc = 0.f;
        for (int t = t0; t < t1; t++) acc += xs[t * Vv + v];
        part[s][v] = acc;
    }
    __syncthreads();
    if (tid < Vv) {
        float acc = part[0][tid] + part[1][tid] + part[2][tid] + part[3][tid] + part[4][tid];
        g_xbar[bc * Vv + tid] = acc * (1.f / (float)Tt);
    }
}

// ============================================================
// K2: rel[b,r,i,j] = tanh(x1[b,r,i] - x2[b,r,j]).  grid = B, block = 256
// ============================================================
__global__ void k2_rel(const float* __restrict__ W1, const float* __restrict__ b1,
                       const float* __restrict__ W2, const float* __restrict__ b2) {
    __shared__ float xb[Cc * Vv];
    __shared__ float w1s[Rr * Cc], w2s[Rr * Cc];
    __shared__ float x1s[Rr * Vv], x2s[Rr * Vv];
    __shared__ float b1s[Rr], b2s[Rr];
    int b = blockIdx.x, tid = threadIdx.x;
    for (int idx = tid; idx < Cc * Vv; idx += 256) xb[idx] = g_xbar[b * (Cc * Vv) + idx];
    for (int idx = tid; idx < Rr * Cc; idx += 256) { w1s[idx] = W1[idx]; w2s[idx] = W2[idx]; }
    if (tid < Rr) { b1s[tid] = b1[tid]; b2s[tid] = b2[tid]; }
    __syncthreads();
    if (tid < Rr * Vv) {
        int r = tid / Vv, v = tid % Vv;
        float a1 = b1s[r], a2 = b2s[r];
        #pragma unroll 8
        for (int c = 0; c < Cc; c++) {
            float xv = xb[c * Vv + v];
            a1 = fmaf(w1s[r * Cc + c], xv, a1);
            a2 = fmaf(w2s[r * Cc + c], xv, a2);
        }
        x1s[tid] = a1; x2s[tid] = a2;
    }
    __syncthreads();
    for (int idx = tid; idx < Rr * Vv * Vv; idx += 256) {
        int r = idx / (Vv * Vv), rem = idx % (Vv * Vv);
        int i = rem / Vv, j = rem % Vv;
        g_rel[b * (Rr * Vv * Vv) + idx] = tanhf(x1s[r * Vv + i] - x2s[r * Vv + j]);
    }
}

// ============================================================
// K3 (tensor-core): per (b,c) block, 128 threads = 4 warps.
// GEMM: z[t][i] = sum_col xtap[t][col] * Bmat[col][i]
//   col = k*28 + v  (Vp=28 pad), K padded to 256, N padded to 32, M = 128.
//   xtap[t][col] = xp_flat[t*28 + col]  (free im2col: overlapping rows!)
//   Bmat[col][i] = Adyn_k[v][i] = sum_r W4[c*9+k,r]*rel[b,r,v,i]+b4+A[v,i]
// A operand: xp flat (row stride 28 floats); B operand (col-major) stored
// as BT[i][col], stride 260 (bank-conflict-free for both frag patterns).
// Inputs pre-rounded to tf32 (cvt.rna) for accuracy.
// Warp w owns t in [32w, 32w+32): 2 m16-tiles x 4 n8-tiles x 32 k8-steps.
// smem: BT 33280B + xp 15360B + w4s/b4s ~330B = ~48.9KB static.
// ============================================================
#define VP 28
#define KK 256
#define BTS 260                   // BT row stride (floats)
#define XPF 3840                  // xp flat floats (>= 127*28+256, 16B mult)

__global__ __launch_bounds__(128) void k3_z(const float* __restrict__ x,
                                            const float* __restrict__ A,
                                            const float* __restrict__ W4,
                                            const float* __restrict__ b4) {
    __shared__ __align__(16) float BT[32 * BTS];   // [i][col]
    __shared__ __align__(16) float xp[XPF];        // flat [(t+8)*28 + v]
    __shared__ float w4s[TSs * Rr];
    __shared__ float b4s[TSs];

    int bc = blockIdx.x;
    int b = bc >> 6, c = bc & 63;
    int tid = threadIdx.x;

    if (tid < TSs * Rr) w4s[tid] = W4[c * (TSs * Rr) + tid];
    if (tid < TSs) b4s[tid] = b4[c * TSs + tid];
    // zero BT and xp (pads must be finite: garbage NaN * 0 = NaN)
    {
        float4 z4 = make_float4(0.f, 0.f, 0.f, 0.f);
        float4* p = reinterpret_cast<float4*>(BT);
        for (int f = tid; f < 32 * BTS / 4; f += 128) p[f] = z4;
        float4* q = reinterpret_cast<float4*>(xp);
        for (int f = tid; f < XPF / 4; f += 128) q[f] = z4;
    }
    __syncthreads();

    // ---- build BT[i][k*28+v] = Adyn_k[v][i] (tf32-rounded) ----
    const float* relg = g_rel + b * (Rr * Vv * Vv);
    for (int vi = tid; vi < Vv * Vv; vi += 128) {
        float r8[Rr];
        #pragma unroll
        for (int r = 0; r < Rr; r++) r8[r] = __ldg(&relg[r * (Vv * Vv) + vi]);
        float av = __ldg(&A[vi]);
        int v = vi / Vv, i = vi - v * Vv;
        #pragma unroll
        for (int k = 0; k < TSs; k++) {
            float acc = b4s[k] + av;
            #pragma unroll
            for (int r = 0; r < Rr; r++) acc = fmaf(w4s[k * Rr + r], r8[r], acc);
            BT[i * BTS + k * VP + v] = to_tf32(acc);
        }
    }
    // ---- fill xp: causal pad 8 rows, then x rows (coalesced reads) ----
    const float* xg = x + (size_t)bc * (Tt * Vv);
    for (int idx = tid; idx < Tt * Vv; idx += 128) {
        int t = idx / Vv, v = idx - t * Vv;
        xp[(t + TSs - 1) * VP + v] = to_tf32(xg[idx]);
    }
    __syncthreads();

    // ---- MMA mainloop ----
    int w = tid >> 5, lane = tid & 31;
    int g = lane >> 2, tig = lane & 3;
    int t0 = w * 32;

    float cfr[2][4][4];
    #pragma unroll
    for (int m = 0; m < 2; m++)
        #pragma unroll
        for (int n = 0; n < 4; n++)
            #pragma unroll
            for (int e = 0; e < 4; e++) cfr[m][n][e] = 0.f;

    const unsigned* xpu = reinterpret_cast<const unsigned*>(xp);
    const unsigned* btu = reinterpret_cast<const unsigned*>(BT);

    #pragma unroll 2
    for (int ks = 0; ks < KK / 8; ks++) {
        int kb = ks * 8;
        unsigned afr[2][4];
        #pragma unroll
        for (int m = 0; m < 2; m++) {
            int r0 = (t0 + m * 16 + g) * VP + kb + tig;
            afr[m][0] = xpu[r0];
            afr[m][1] = xpu[r0 + 8 * VP];
            afr[m][2] = xpu[r0 + 4];
            afr[m][3] = xpu[r0 + 8 * VP + 4];
        }
        unsigned bfr[4][2];
        #pragma unroll
        for (int n = 0; n < 4; n++) {
            int rb = (n * 8 + g) * BTS + kb + tig;
            bfr[n][0] = btu[rb];
            bfr[n][1] = btu[rb + 4];
        }
        #pragma unroll
        for (int m = 0; m < 2; m++)
            #pragma unroll
            for (int n = 0; n < 4; n++)
                mma_tf32(cfr[m][n], afr[m], bfr[n]);
    }
    __syncthreads();               // done reading xp; alias as zstage

    // ---- write C frags to zstage [t][25], then coalesced copy out ----
    float* zst = xp;
    #pragma unroll
    for (int m = 0; m < 2; m++) {
        int tr = t0 + m * 16 + g;
        #pragma unroll
        for (int n = 0; n < 4; n++) {
            int i0 = n * 8 + 2 * tig;
            if (i0 < Vv) {
                zst[tr * Vv + i0]       = cfr[m][n][0];
                zst[(tr + 8) * Vv + i0] = cfr[m][n][2];
            }
            if (i0 + 1 < Vv) {
                zst[tr * Vv + i0 + 1]       = cfr[m][n][1];
                zst[(tr + 8) * Vv + i0 + 1] = cfr[m][n][3];
            }
        }
    }
    __syncthreads();
    float4* zg4 = reinterpret_cast<float4*>(g_z + (size_t)bc * (Tt * Vv));
    const float4* zs4 = reinterpret_cast<const float4*>(zst);
    for (int f = tid; f < Tt * Vv / 4; f += 128) zg4[f] = zs4[f];
}

// ============================================================
// K4: out[b,o,n] = b3[o] + sum_c W3[o,c] * z[b,c,n]
// grid = (25 n-tiles of 128, B), block = 256 (8 warps), cp.async 2-stage.
// ============================================================
#define CCH 16
__global__ __launch_bounds__(256) void k4_conv3(const float* __restrict__ W3,
                                                const float* __restrict__ b3,
                                                float* __restrict__ out) {
    __shared__ __align__(16) float w3t[Cc * OUTo];       // [c][o] 16KB
    __shared__ __align__(16) float zs[2][CCH * 128];     // 2 x 8KB
    int nt = blockIdx.x, b = blockIdx.y;
    int tid = threadIdx.x;

    for (int idx = tid; idx < OUTo * Cc; idx += 256) {
        int o = idx >> 6, c = idx & 63;
        w3t[c * OUTo + o] = W3[idx];
    }

    const float* zbase = g_z + (size_t)b * (Cc * Tt * Vv) + nt * 128;
    auto issue = [&](int ci, int buf) {
        #pragma unroll
        for (int rep = 0; rep < 2; rep++) {
            int f = tid + rep * 256;
            int row = f >> 5, seg = f & 31;
            cp_async16(&zs[buf][row * 128 + seg * 4],
                       zbase + (size_t)(ci * CCH + row) * (Tt * Vv) + seg * 4);
        }
        asm volatile("cp.async.commit_group;\n" ::: "memory");
    };

    issue(0, 0);

    int w = tid >> 5, lane = tid & 31;
    int o0 = w * 8, n0 = lane * 4;

    ull acc[4][4];
    #pragma unroll
    for (int p = 0; p < 4; p++)
        #pragma unroll
        for (int qq = 0; qq < 4; qq++) acc[p][qq] = 0ull;

    #pragma unroll 1
    for (int ci = 0; ci < Cc / CCH; ci++) {
        if (ci < Cc / CCH - 1) issue(ci + 1, (ci + 1) & 1);
        if (ci < Cc / CCH - 1) { asm volatile("cp.async.wait_group 1;\n" ::: "memory"); }
        else                   { asm volatile("cp.async.wait_group 0;\n" ::: "memory"); }
        __syncthreads();
        const float* zb = zs[ci & 1];
        #pragma unroll 4
        for (int cl = 0; cl < CCH; cl++) {
            int c = ci * CCH + cl;
            const ulonglong2* wp =
                reinterpret_cast<const ulonglong2*>(&w3t[c * OUTo + o0]);
            ulonglong2 wa = wp[0];
            ulonglong2 wb = wp[1];
            float4 z4 = *reinterpret_cast<const float4*>(&zb[cl * 128 + n0]);
            ull zs0 = splat2(z4.x), zs1 = splat2(z4.y);
            ull zs2 = splat2(z4.z), zs3 = splat2(z4.w);
            ffma2(acc[0][0], wa.x, zs0); ffma2(acc[0][1], wa.x, zs1);
            ffma2(acc[0][2], wa.x, zs2); ffma2(acc[0][3], wa.x, zs3);
            ffma2(acc[1][0], wa.y, zs0); ffma2(acc[1][1], wa.y, zs1);
            ffma2(acc[1][2], wa.y, zs2); ffma2(acc[1][3], wa.y, zs3);
            ffma2(acc[2][0], wb.x, zs0); ffma2(acc[2][1], wb.x, zs1);
            ffma2(acc[2][2], wb.x, zs2); ffma2(acc[2][3], wb.x, zs3);
            ffma2(acc[3][0], wb.y, zs0); ffma2(acc[3][1], wb.y, zs1);
            ffma2(acc[3][2], wb.y, zs2); ffma2(acc[3][3], wb.y, zs3);
        }
        __syncthreads();
    }

    float* ob = out + (size_t)b * OUTo * (Tt * Vv) + nt * 128 + n0;
    #pragma unroll
    for (int p = 0; p < 4; p++) {
        int oA = o0 + 2 * p, oB = oA + 1;
        float bA = __ldg(&b3[oA]), bB = __ldg(&b3[oB]);
        float2 f0 = lo_hi(acc[p][0]), f1 = lo_hi(acc[p][1]);
        float2 f2 = lo_hi(acc[p][2]), f3 = lo_hi(acc[p][3]);
        float4 vA = make_float4(f0.x + bA, f1.x + bA, f2.x + bA, f3.x + bA);
        float4 vB = make_float4(f0.y + bB, f1.y + bB, f2.y + bB, f3.y + bB);
        *reinterpret_cast<float4*>(ob + (size_t)oA * (Tt * Vv)) = vA;
        *reinterpret_cast<float4*>(ob + (size_t)oB * (Tt * Vv)) = vB;
    }
}

// ============================================================
extern "C" void kernel_launch(void* const* d_in, const int* in_sizes, int n_in,
                              void* d_out, int out_size) {
    const float* x  = (const float*)d_in[0];
    const float* A  = (const float*)d_in[1];
    const float* W1 = (const float*)d_in[2];
    const float* b1 = (const float*)d_in[3];
    const float* W2 = (const float*)d_in[4];
    const float* b2 = (const float*)d_in[5];
    const float* W4 = (const float*)d_in[6];
    const float* b4 = (const float*)d_in[7];
    const float* W3 = (const float*)d_in[8];
    const float* b3 = (const float*)d_in[9];
    float* out = (float*)d_out;

    k1_xbar<<<Bb * Cc, 128>>>(x);
    k2_rel<<<Bb, 256>>>(W1, b1, W2, b2);
    k3_z<<<Bb * Cc, 128>>>(x, A, W4, b4);
    k4_conv3<<<dim3(25, Bb), 256>>>(W3, b3, out);
}

// round 7
// speedup vs baseline: 1.3902x; 1.0007x over previous
#include <cuda_runtime.h>
#include <cstdint>

// Problem constants
#define Bb 64
#define Cc 64
#define Tt 128
#define Vv 25
#define Rr 8
#define TSs 9
#define OUTo 64

typedef unsigned long long ull;

// Scratch (device globals — no allocation allowed)
__device__ float g_xbar[Bb * Cc * Vv];          // (b,c,v) mean over t
__device__ float g_rel[Bb * Rr * Vv * Vv];      // (b,r,i,j)
__device__ float g_z[Bb * Cc * Tt * Vv];        // (b,c,t,v) intermediate

// ---------- packed f32x2 helpers ----------
__device__ __forceinline__ void ffma2(ull& acc, ull a, ull b) {
    asm("fma.rn.f32x2 %0, %1, %2, %0;" : "+l"(acc) : "l"(a), "l"(b));
}
__device__ __forceinline__ ull splat2(float x) {
    ull r;
    unsigned int xu = __float_as_uint(x);
    asm("mov.b64 %0, {%1, %1};" : "=l"(r) : "r"(xu));
    return r;
}
__device__ __forceinline__ float2 lo_hi(ull v) {
    float2 f;
    asm("mov.b64 {%0, %1}, %2;" : "=f"(f.x), "=f"(f.y) : "l"(v));
    return f;
}
__device__ __forceinline__ void cp_async16(float* smem_dst, const float* gmem_src) {
    unsigned s = (unsigned)__cvta_generic_to_shared(smem_dst);
    asm volatile("cp.async.cg.shared.global [%0], [%1], 16;\n" :: "r"(s), "l"(gmem_src));
}
__device__ __forceinline__ float to_tf32(float x) {
    unsigned u;
    asm("cvt.rna.tf32.f32 %0, %1;" : "=r"(u) : "f"(x));
    return __uint_as_float(u);
}
__device__ __forceinline__ void mma_tf32(float* c, const unsigned* a, const unsigned* b) {
    asm volatile(
        "mma.sync.aligned.m16n8k8.row.col.f32.tf32.tf32.f32 "
        "{%0,%1,%2,%3}, {%4,%5,%6,%7}, {%8,%9}, {%0,%1,%2,%3};"
        : "+f"(c[0]), "+f"(c[1]), "+f"(c[2]), "+f"(c[3])
        : "r"(a[0]), "r"(a[1]), "r"(a[2]), "r"(a[3]), "r"(b[0]), "r"(b[1]));
}

// ============================================================
// K1: xbar[b,c,v] = mean_t x[b,c,t,v].  grid = B*C, block = 128
// ============================================================
__global__ void k1_xbar(const float* __restrict__ x) {
    __shared__ __align__(16) float xs[Tt * Vv];
    __shared__ float part[5][Vv];
    int bc = blockIdx.x, tid = threadIdx.x;
    const float4* xg4 = reinterpret_cast<const float4*>(x + (size_t)bc * (Tt * Vv));
    float4* xs4 = reinterpret_cast<float4*>(xs);
    for (int f = tid; f < Tt * Vv / 4; f += 128) xs4[f] = xg4[f];
    __syncthreads();
    if (tid < 125) {
        int v = tid % 25, s = tid / 25;
        int t0 = s * 26;
        int t1 = t0 + 26; if (t1 > Tt) t1 = Tt;
        float acc = 0.f;
        for (int t = t0; t < t1; t++) acc += xs[t * Vv + v];
        part[s][v] = acc;
    }
    __syncthreads();
    if (tid < Vv) {
        float acc = part[0][tid] + part[1][tid] + part[2][tid] + part[3][tid] + part[4][tid];
        g_xbar[bc * Vv + tid] = acc * (1.f / (float)Tt);
    }
}

// ============================================================
// K2: rel[b,r,i,j] = tanh(x1[b,r,i] - x2[b,r,j]).  grid = B, block = 256
// ============================================================
__global__ void k2_rel(const float* __restrict__ W1, const float* __restrict__ b1,
                       const float* __restrict__ W2, const float* __restrict__ b2) {
    __shared__ float xb[Cc * Vv];
    __shared__ float w1s[Rr * Cc], w2s[Rr * Cc];
    __shared__ float x1s[Rr * Vv], x2s[Rr * Vv];
    __shared__ float b1s[Rr], b2s[Rr];
    int b = blockIdx.x, tid = threadIdx.x;
    for (int idx = tid; idx < Cc * Vv; idx += 256) xb[idx] = g_xbar[b * (Cc * Vv) + idx];
    for (int idx = tid; idx < Rr * Cc; idx += 256) { w1s[idx] = W1[idx]; w2s[idx] = W2[idx]; }
    if (tid < Rr) { b1s[tid] = b1[tid]; b2s[tid] = b2[tid]; }
    __syncthreads();
    if (tid < Rr * Vv) {
        int r = tid / Vv, v = tid % Vv;
        float a1 = b1s[r], a2 = b2s[r];
        #pragma unroll 8
        for (int c = 0; c < Cc; c++) {
            float xv = xb[c * Vv + v];
            a1 = fmaf(w1s[r * Cc + c], xv, a1);
            a2 = fmaf(w2s[r * Cc + c], xv, a2);
        }
        x1s[tid] = a1; x2s[tid] = a2;
    }
    __syncthreads();
    for (int idx = tid; idx < Rr * Vv * Vv; idx += 256) {
        int r = idx / (Vv * Vv), rem = idx % (Vv * Vv);
        int i = rem / Vv, j = rem % Vv;
        g_rel[b * (Rr * Vv * Vv) + idx] = tanhf(x1s[r * Vv + i] - x2s[r * Vv + j]);
    }
}

// ============================================================
// K3 (tensor-core): per (b,c) block, 128 threads = 4 warps.
// GEMM: z[t][i] = sum_col xtap[t][col] * Bmat[col][i]
//   col = k*28 + v  (Vp=28 pad), K padded to 256, N padded to 32, M = 128.
//   xtap[t][col] = xp_flat[t*28 + col]  (free im2col: overlapping rows!)
//   Bmat[col][i] = Adyn_k[v][i] = sum_r W4[c*9+k,r]*rel[b,r,v,i]+b4+A[v,i]
// A operand: xp flat (row stride 28 floats); B operand (col-major) stored
// as BT[i][col], stride 260 (bank-conflict-free for both frag patterns).
// Inputs pre-rounded to tf32 (cvt.rna) for accuracy.
// Warp w owns t in [32w, 32w+32): 2 m16-tiles x 4 n8-tiles x 32 k8-steps.
// smem: BT 33280B + xp 15360B + w4s/b4s ~330B = ~48.9KB static.
// ============================================================
#define VP 28
#define KK 256
#define BTS 260                   // BT row stride (floats)
#define XPF 3840                  // xp flat floats (>= 127*28+256, 16B mult)

__global__ __launch_bounds__(128) void k3_z(const float* __restrict__ x,
                                            const float* __restrict__ A,
                                            const float* __restrict__ W4,
                                            const float* __restrict__ b4) {
    __shared__ __align__(16) float BT[32 * BTS];   // [i][col]
    __shared__ __align__(16) float xp[XPF];        // flat [(t+8)*28 + v]
    __shared__ float w4s[TSs * Rr];
    __shared__ float b4s[TSs];

    int bc = blockIdx.x;
    int b = bc >> 6, c = bc & 63;
    int tid = threadIdx.x;

    if (tid < TSs * Rr) w4s[tid] = W4[c * (TSs * Rr) + tid];
    if (tid < TSs) b4s[tid] = b4[c * TSs + tid];
    // zero BT and xp (pads must be finite: garbage NaN * 0 = NaN)
    {
        float4 z4 = make_float4(0.f, 0.f, 0.f, 0.f);
        float4* p = reinterpret_cast<float4*>(BT);
        for (int f = tid; f < 32 * BTS / 4; f += 128) p[f] = z4;
        float4* q = reinterpret_cast<float4*>(xp);
        for (int f = tid; f < XPF / 4; f += 128) q[f] = z4;
    }
    __syncthreads();

    // ---- build BT[i][k*28+v] = Adyn_k[v][i] (tf32-rounded) ----
    const float* relg = g_rel + b * (Rr * Vv * Vv);
    for (int vi = tid; vi < Vv * Vv; vi += 128) {
        float r8[Rr];
        #pragma unroll
        for (int r = 0; r < Rr; r++) r8[r] = __ldg(&relg[r * (Vv * Vv) + vi]);
        float av = __ldg(&A[vi]);
        int v = vi / Vv, i = vi - v * Vv;
        #pragma unroll
        for (int k = 0; k < TSs; k++) {
            float acc = b4s[k] + av;
            #pragma unroll
            for (int r = 0; r < Rr; r++) acc = fmaf(w4s[k * Rr + r], r8[r], acc);
            BT[i * BTS + k * VP + v] = to_tf32(acc);
        }
    }
    // ---- fill xp: causal pad 8 rows, then x rows (coalesced reads) ----
    const float* xg = x + (size_t)bc * (Tt * Vv);
    for (int idx = tid; idx < Tt * Vv; idx += 128) {
        int t = idx / Vv, v = idx - t * Vv;
        xp[(t + TSs - 1) * VP + v] = to_tf32(xg[idx]);
    }
    __syncthreads();

    // ---- MMA mainloop ----
    int w = tid >> 5, lane = tid & 31;
    int g = lane >> 2, tig = lane & 3;
    int t0 = w * 32;

    float cfr[2][4][4];
    #pragma unroll
    for (int m = 0; m < 2; m++)
        #pragma unroll
        for (int n = 0; n < 4; n++)
            #pragma unroll
            for (int e = 0; e < 4; e++) cfr[m][n][e] = 0.f;

    const unsigned* xpu = reinterpret_cast<const unsigned*>(xp);
    const unsigned* btu = reinterpret_cast<const unsigned*>(BT);

    #pragma unroll 2
    for (int ks = 0; ks < KK / 8; ks++) {
        int kb = ks * 8;
        unsigned afr[2][4];
        #pragma unroll
        for (int m = 0; m < 2; m++) {
            int r0 = (t0 + m * 16 + g) * VP + kb + tig;
            afr[m][0] = xpu[r0];
            afr[m][1] = xpu[r0 + 8 * VP];
            afr[m][2] = xpu[r0 + 4];
            afr[m][3] = xpu[r0 + 8 * VP + 4];
        }
        unsigned bfr[4][2];
        #pragma unroll
        for (int n = 0; n < 4; n++) {
            int rb = (n * 8 + g) * BTS + kb + tig;
            bfr[n][0] = btu[rb];
            bfr[n][1] = btu[rb + 4];
        }
        #pragma unroll
        for (int m = 0; m < 2; m++)
            #pragma unroll
            for (int n = 0; n < 4; n++)
                mma_tf32(cfr[m][n], afr[m], bfr[n]);
    }
    __syncthreads();               // done reading xp; alias as zstage

    // ---- write C frags to zstage [t][25], then coalesced copy out ----
    float* zst = xp;
    #pragma unroll
    for (int m = 0; m < 2; m++) {
        int tr = t0 + m * 16 + g;
        #pragma unroll
        for (int n = 0; n < 4; n++) {
            int i0 = n * 8 + 2 * tig;
            if (i0 < Vv) {
                zst[tr * Vv + i0]       = cfr[m][n][0];
                zst[(tr + 8) * Vv + i0] = cfr[m][n][2];
            }
            if (i0 + 1 < Vv) {
                zst[tr * Vv + i0 + 1]       = cfr[m][n][1];
                zst[(tr + 8) * Vv + i0 + 1] = cfr[m][n][3];
            }
        }
    }
    __syncthreads();
    float4* zg4 = reinterpret_cast<float4*>(g_z + (size_t)bc * (Tt * Vv));
    const float4* zs4 = reinterpret_cast<const float4*>(zst);
    for (int f = tid; f < Tt * Vv / 4; f += 128) zg4[f] = zs4[f];
}

// ============================================================
// K4: out[b,o,n] = b3[o] + sum_c W3[o,c] * z[b,c,n]
// grid = (25 n-tiles of 128, B), block = 256 (8 warps), cp.async 2-stage.
// ============================================================
#define CCH 16
__global__ __launch_bounds__(256) void k4_conv3(const float* __restrict__ W3,
                                                const float* __restrict__ b3,
                                                float* __restrict__ out) {
    __shared__ __align__(16) float w3t[Cc * OUTo];       // [c][o] 16KB
    __shared__ __align__(16) float zs[2][CCH * 128];     // 2 x 8KB
    int nt = blockIdx.x, b = blockIdx.y;
    int tid = threadIdx.x;

    for (int idx = tid; idx < OUTo * Cc; idx += 256) {
        int o = idx >> 6, c = idx & 63;
        w3t[c * OUTo + o] = W3[idx];
    }

    const float* zbase = g_z + (size_t)b * (Cc * Tt * Vv) + nt * 128;
    auto issue = [&](int ci, int buf) {
        #pragma unroll
        for (int rep = 0; rep < 2; rep++) {
            int f = tid + rep * 256;
            int row = f >> 5, seg = f & 31;
            cp_async16(&zs[buf][row * 128 + seg * 4],
                       zbase + (size_t)(ci * CCH + row) * (Tt * Vv) + seg * 4);
        }
        asm volatile("cp.async.commit_group;\n" ::: "memory");
    };

    issue(0, 0);

    int w = tid >> 5, lane = tid & 31;
    int o0 = w * 8, n0 = lane * 4;

    ull acc[4][4];
    #pragma unroll
    for (int p = 0; p < 4; p++)
        #pragma unroll
        for (int qq = 0; qq < 4; qq++) acc[p][qq] = 0ull;

    #pragma unroll 1
    for (int ci = 0; ci < Cc / CCH; ci++) {
        if (ci < Cc / CCH - 1) issue(ci + 1, (ci + 1) & 1);
        if (ci < Cc / CCH - 1) { asm volatile("cp.async.wait_group 1;\n" ::: "memory"); }
        else                   { asm volatile("cp.async.wait_group 0;\n" ::: "memory"); }
        __syncthreads();
        const float* zb = zs[ci & 1];
        #pragma unroll 4
        for (int cl = 0; cl < CCH; cl++) {
            int c = ci * CCH + cl;
            const ulonglong2* wp =
                reinterpret_cast<const ulonglong2*>(&w3t[c * OUTo + o0]);
            ulonglong2 wa = wp[0];
            ulonglong2 wb = wp[1];
            float4 z4 = *reinterpret_cast<const float4*>(&zb[cl * 128 + n0]);
            ull zs0 = splat2(z4.x), zs1 = splat2(z4.y);
            ull zs2 = splat2(z4.z), zs3 = splat2(z4.w);
            ffma2(acc[0][0], wa.x, zs0); ffma2(acc[0][1], wa.x, zs1);
            ffma2(acc[0][2], wa.x, zs2); ffma2(acc[0][3], wa.x, zs3);
            ffma2(acc[1][0], wa.y, zs0); ffma2(acc[1][1], wa.y, zs1);
            ffma2(acc[1][2], wa.y, zs2); ffma2(acc[1][3], wa.y, zs3);
            ffma2(acc[2][0], wb.x, zs0); ffma2(acc[2][1], wb.x, zs1);
            ffma2(acc[2][2], wb.x, zs2); ffma2(acc[2][3], wb.x, zs3);
            ffma2(acc[3][0], wb.y, zs0); ffma2(acc[3][1], wb.y, zs1);
            ffma2(acc[3][2], wb.y, zs2); ffma2(acc[3][3], wb.y, zs3);
        }
        __syncthreads();
    }

    float* ob = out + (size_t)b * OUTo * (Tt * Vv) + nt * 128 + n0;
    #pragma unroll
    for (int p = 0; p < 4; p++) {
        int oA = o0 + 2 * p, oB = oA + 1;
        float bA = __ldg(&b3[oA]), bB = __ldg(&b3[oB]);
        float2 f0 = lo_hi(acc[p][0]), f1 = lo_hi(acc[p][1]);
        float2 f2 = lo_hi(acc[p][2]), f3 = lo_hi(acc[p][3]);
        float4 vA = make_float4(f0.x + bA, f1.x + bA, f2.x + bA, f3.x + bA);
        float4 vB = make_float4(f0.y + bB, f1.y + bB, f2.y + bB, f3.y + bB);
        *reinterpret_cast<float4*>(ob + (size_t)oA * (Tt * Vv)) = vA;
        *reinterpret_cast<float4*>(ob + (size_t)oB * (Tt * Vv)) = vB;
    }
}

// ============================================================
extern "C" void kernel_launch(void* const* d_in, const int* in_sizes, int n_in,
                              void* d_out, int out_size) {
    const float* x  = (const float*)d_in[0];
    const float* A  = (const float*)d_in[1];
    const float* W1 = (const float*)d_in[2];
    const float* b1 = (const float*)d_in[3];
    const float* W2 = (const float*)d_in[4];
    const float* b2 = (const float*)d_in[5];
    const float* W4 = (const float*)d_in[6];
    const float* b4 = (const float*)d_in[7];
    const float* W3 = (const float*)d_in[8];
    const float* b3 = (const float*)d_in[9];
    float* out = (float*)d_out;

    k1_xbar<<<Bb * Cc, 128>>>(x);
    k2_rel<<<Bb, 256>>>(W1, b1, W2, b2);
    k3_z<<<Bb * Cc, 128>>>(x, A, W4, b4);
    k4_conv3<<<dim3(25, Bb), 256>>>(W3, b3, out);
}

// round 8
// speedup vs baseline: 1.6206x; 1.1658x over previous
#include <cuda_runtime.h>
#include <cstdint>

// Problem constants
#define Bb 64
#define Cc 64
#define Tt 128
#define Vv 25
#define Rr 8
#define TSs 9
#define OUTo 64

typedef unsigned long long ull;

// Scratch (device globals — no allocation allowed)
__device__ float g_xbar[Bb * Cc * Vv];          // (b,c,v) mean over t
__device__ float g_rel[Bb * Rr * Vv * Vv];      // (b,r,i,j)
__device__ float g_z[Bb * Cc * Tt * Vv];        // (b,c,t,v), tf32-rounded

// ---------- helpers ----------
__device__ __forceinline__ void cp_async16(float* smem_dst, const float* gmem_src) {
    unsigned s = (unsigned)__cvta_generic_to_shared(smem_dst);
    asm volatile("cp.async.cg.shared.global [%0], [%1], 16;\n" :: "r"(s), "l"(gmem_src));
}
__device__ __forceinline__ float to_tf32(float x) {
    unsigned u;
    asm("cvt.rna.tf32.f32 %0, %1;" : "=r"(u) : "f"(x));
    return __uint_as_float(u);
}
__device__ __forceinline__ void mma_tf32(float* c, const unsigned* a, const unsigned* b) {
    asm volatile(
        "mma.sync.aligned.m16n8k8.row.col.f32.tf32.tf32.f32 "
        "{%0,%1,%2,%3}, {%4,%5,%6,%7}, {%8,%9}, {%0,%1,%2,%3};"
        : "+f"(c[0]), "+f"(c[1]), "+f"(c[2]), "+f"(c[3])
        : "r"(a[0]), "r"(a[1]), "r"(a[2]), "r"(a[3]), "r"(b[0]), "r"(b[1]));
}

// ============================================================
// K1: xbar[b,c,v] = mean_t x[b,c,t,v].  grid = B*C, block = 128
// ============================================================
__global__ void k1_xbar(const float* __restrict__ x) {
    __shared__ __align__(16) float xs[Tt * Vv];
    __shared__ float part[5][Vv];
    int bc = blockIdx.x, tid = threadIdx.x;
    const float4* xg4 = reinterpret_cast<const float4*>(x + (size_t)bc * (Tt * Vv));
    float4* xs4 = reinterpret_cast<float4*>(xs);
    for (int f = tid; f < Tt * Vv / 4; f += 128) xs4[f] = xg4[f];
    __syncthreads();
    if (tid < 125) {
        int v = tid % 25, s = tid / 25;
        int t0 = s * 26;
        int t1 = t0 + 26; if (t1 > Tt) t1 = Tt;
        float acc = 0.f;
        for (int t = t0; t < t1; t++) acc += xs[t * Vv + v];
        part[s][v] = acc;
    }
    __syncthreads();
    if (tid < Vv) {
        float acc = part[0][tid] + part[1][tid] + part[2][tid] + part[3][tid] + part[4][tid];
        g_xbar[bc * Vv + tid] = acc * (1.f / (float)Tt);
    }
}

// ============================================================
// K2: rel[b,r,i,j] = tanh(x1[b,r,i] - x2[b,r,j]).  grid = B, block = 256
// ============================================================
__global__ void k2_rel(const float* __restrict__ W1, const float* __restrict__ b1,
                       const float* __restrict__ W2, const float* __restrict__ b2) {
    __shared__ float xb[Cc * Vv];
    __shared__ float w1s[Rr * Cc], w2s[Rr * Cc];
    __shared__ float x1s[Rr * Vv], x2s[Rr * Vv];
    __shared__ float b1s[Rr], b2s[Rr];
    int b = blockIdx.x, tid = threadIdx.x;
    for (int idx = tid; idx < Cc * Vv; idx += 256) xb[idx] = g_xbar[b * (Cc * Vv) + idx];
    for (int idx = tid; idx < Rr * Cc; idx += 256) { w1s[idx] = W1[idx]; w2s[idx] = W2[idx]; }
    if (tid < Rr) { b1s[tid] = b1[tid]; b2s[tid] = b2[tid]; }
    __syncthreads();
    if (tid < Rr * Vv) {
        int r = tid / Vv, v = tid % Vv;
        float a1 = b1s[r], a2 = b2s[r];
        #pragma unroll 8
        for (int c = 0; c < Cc; c++) {
            float xv = xb[c * Vv + v];
            a1 = fmaf(w1s[r * Cc + c], xv, a1);
            a2 = fmaf(w2s[r * Cc + c], xv, a2);
        }
        x1s[tid] = a1; x2s[tid] = a2;
    }
    __syncthreads();
    for (int idx = tid; idx < Rr * Vv * Vv; idx += 256) {
        int r = idx / (Vv * Vv), rem = idx % (Vv * Vv);
        int i = rem / Vv, j = rem % Vv;
        g_rel[b * (Rr * Vv * Vv) + idx] = tanhf(x1s[r * Vv + i] - x2s[r * Vv + j]);
    }
}

// ============================================================
// K3 (tensor-core): per (b,c) block, 128 threads = 4 warps.
// GEMM: z[t][i] = sum_col xtap[t][col] * Bmat[col][i],  col = k*28+v.
// xtap[t][col] = xp_flat[t*28 + col]  (free im2col via overlapping rows).
// Epilogue stores z tf32-ROUNDED (k4 consumes it through tf32 MMA).
// ============================================================
#define VP 28
#define KK 256
#define BTS 260                   // BT row stride (floats)
#define XPF 3840                  // xp flat floats (>= 127*28+256, 16B mult)

__global__ __launch_bounds__(128) void k3_z(const float* __restrict__ x,
                                            const float* __restrict__ A,
                                            const float* __restrict__ W4,
                                            const float* __restrict__ b4) {
    __shared__ __align__(16) float BT[32 * BTS];   // [i][col]
    __shared__ __align__(16) float xp[XPF];        // flat [(t+8)*28 + v]
    __shared__ float w4s[TSs * Rr];
    __shared__ float b4s[TSs];

    int bc = blockIdx.x;
    int b = bc >> 6, c = bc & 63;
    int tid = threadIdx.x;

    if (tid < TSs * Rr) w4s[tid] = W4[c * (TSs * Rr) + tid];
    if (tid < TSs) b4s[tid] = b4[c * TSs + tid];
    {
        float4 z4 = make_float4(0.f, 0.f, 0.f, 0.f);
        float4* p = reinterpret_cast<float4*>(BT);
        for (int f = tid; f < 32 * BTS / 4; f += 128) p[f] = z4;
        float4* q = reinterpret_cast<float4*>(xp);
        for (int f = tid; f < XPF / 4; f += 128) q[f] = z4;
    }
    __syncthreads();

    // ---- build BT[i][k*28+v] = Adyn_k[v][i] (tf32-rounded) ----
    const float* relg = g_rel + b * (Rr * Vv * Vv);
    for (int vi = tid; vi < Vv * Vv; vi += 128) {
        float r8[Rr];
        #pragma unroll
        for (int r = 0; r < Rr; r++) r8[r] = __ldg(&relg[r * (Vv * Vv) + vi]);
        float av = __ldg(&A[vi]);
        int v = vi / Vv, i = vi - v * Vv;
        #pragma unroll
        for (int k = 0; k < TSs; k++) {
            float acc = b4s[k] + av;
            #pragma unroll
            for (int r = 0; r < Rr; r++) acc = fmaf(w4s[k * Rr + r], r8[r], acc);
            BT[i * BTS + k * VP + v] = to_tf32(acc);
        }
    }
    // ---- fill xp: causal pad 8 rows, then x rows (coalesced reads) ----
    const float* xg = x + (size_t)bc * (Tt * Vv);
    for (int idx = tid; idx < Tt * Vv; idx += 128) {
        int t = idx / Vv, v = idx - t * Vv;
        xp[(t + TSs - 1) * VP + v] = to_tf32(xg[idx]);
    }
    __syncthreads();

    // ---- MMA mainloop ----
    int w = tid >> 5, lane = tid & 31;
    int g = lane >> 2, tig = lane & 3;
    int t0 = w * 32;

    float cfr[2][4][4];
    #pragma unroll
    for (int m = 0; m < 2; m++)
        #pragma unroll
        for (int n = 0; n < 4; n++)
            #pragma unroll
            for (int e = 0; e < 4; e++) cfr[m][n][e] = 0.f;

    const unsigned* xpu = reinterpret_cast<const unsigned*>(xp);
    const unsigned* btu = reinterpret_cast<const unsigned*>(BT);

    #pragma unroll 2
    for (int ks = 0; ks < KK / 8; ks++) {
        int kb = ks * 8;
        unsigned afr[2][4];
        #pragma unroll
        for (int m = 0; m < 2; m++) {
            int r0 = (t0 + m * 16 + g) * VP + kb + tig;
            afr[m][0] = xpu[r0];
            afr[m][1] = xpu[r0 + 8 * VP];
            afr[m][2] = xpu[r0 + 4];
            afr[m][3] = xpu[r0 + 8 * VP + 4];
        }
        unsigned bfr[4][2];
        #pragma unroll
        for (int n = 0; n < 4; n++) {
            int rb = (n * 8 + g) * BTS + kb + tig;
            bfr[n][0] = btu[rb];
            bfr[n][1] = btu[rb + 4];
        }
        #pragma unroll
        for (int m = 0; m < 2; m++)
            #pragma unroll
            for (int n = 0; n < 4; n++)
                mma_tf32(cfr[m][n], afr[m], bfr[n]);
    }
    __syncthreads();               // done reading xp; alias as zstage

    // ---- write C frags (tf32-rounded) to zstage [t][25], then copy out ----
    float* zst = xp;
    #pragma unroll
    for (int m = 0; m < 2; m++) {
        int tr = t0 + m * 16 + g;
        #pragma unroll
        for (int n = 0; n < 4; n++) {
            int i0 = n * 8 + 2 * tig;
            if (i0 < Vv) {
                zst[tr * Vv + i0]       = to_tf32(cfr[m][n][0]);
                zst[(tr + 8) * Vv + i0] = to_tf32(cfr[m][n][2]);
            }
            if (i0 + 1 < Vv) {
                zst[tr * Vv + i0 + 1]       = to_tf32(cfr[m][n][1]);
                zst[(tr + 8) * Vv + i0 + 1] = to_tf32(cfr[m][n][3]);
            }
        }
    }
    __syncthreads();
    float4* zg4 = reinterpret_cast<float4*>(g_z + (size_t)bc * (Tt * Vv));
    const float4* zs4 = reinterpret_cast<const float4*>(zst);
    for (int f = tid; f < Tt * Vv / 4; f += 128) zg4[f] = zs4[f];
}

// ============================================================
// K4 (tensor-core): out[b,o,n] = b3[o] + sum_c W3[o,c] * z[b,c,n]
// Per block: n-tile of 128 (M-dim, 8 warps x m16), o = 64 (8 n8-tiles),
// K = c = 64 in 4 cp.async double-buffered chunks of 16.
// zs stride 136: A-frag banks (8*tig+g) conflict-free.
// w3s stride 68: B-frag banks (4*g+tig) conflict-free.
// smem: w3s 17408 + zs 2x8704 + b3s 256 = ~35KB static.
// ============================================================
#define ZSS 136
#define W3S 68
__global__ __launch_bounds__(256) void k4_mma(const float* __restrict__ W3,
                                              const float* __restrict__ b3,
                                              float* __restrict__ out) {
    __shared__ __align__(16) float w3s[OUTo * W3S];
    __shared__ __align__(16) float zs[2][16 * ZSS];
    __shared__ float b3s[OUTo];
    int nt = blockIdx.x, b = blockIdx.y;
    int tid = threadIdx.x;

    for (int idx = tid; idx < OUTo * Cc; idx += 256) {
        int o = idx >> 6, c = idx & 63;
        w3s[o * W3S + c] = to_tf32(W3[idx]);
    }
    if (tid < OUTo) b3s[tid] = b3[tid];

    const float* zbase = g_z + (size_t)b * (Cc * Tt * Vv) + nt * 128;
    auto issue = [&](int ci, int buf) {
        #pragma unroll
        for (int rep = 0; rep < 2; rep++) {
            int f = tid + rep * 256;
            int row = f >> 5, seg = f & 31;
            cp_async16(&zs[buf][row * ZSS + seg * 4],
                       zbase + (size_t)(ci * 16 + row) * (Tt * Vv) + seg * 4);
        }
        asm volatile("cp.async.commit_group;\n" ::: "memory");
    };
    issue(0, 0);

    int w = tid >> 5, lane = tid & 31;
    int g = lane >> 2, tig = lane & 3;
    int nw = w * 16;

    float cfr[8][4];
    #pragma unroll
    for (int ot = 0; ot < 8; ot++)
        #pragma unroll
        for (int e = 0; e < 4; e++) cfr[ot][e] = 0.f;

    #pragma unroll 1
    for (int ci = 0; ci < 4; ci++) {
        if (ci < 3) { issue(ci + 1, (ci + 1) & 1);
                      asm volatile("cp.async.wait_group 1;\n" ::: "memory"); }
        else        { asm volatile("cp.async.wait_group 0;\n" ::: "memory"); }
        __syncthreads();           // chunk ci visible (covers w3s/b3s on ci=0)
        const unsigned* zbu = reinterpret_cast<const unsigned*>(zs[ci & 1]);
        const unsigned* wtu = reinterpret_cast<const unsigned*>(w3s);
        #pragma unroll
        for (int ks = 0; ks < 2; ks++) {
            int kb = ks * 8;
            unsigned afr[4];
            afr[0] = zbu[(kb + tig) * ZSS + nw + g];           // A[m=g][k=tig]
            afr[1] = zbu[(kb + tig) * ZSS + nw + g + 8];       // A[m=g+8][k=tig]
            afr[2] = zbu[(kb + tig + 4) * ZSS + nw + g];       // A[m=g][k=tig+4]
            afr[3] = zbu[(kb + tig + 4) * ZSS + nw + g + 8];   // A[m=g+8][k=tig+4]
            int cg = ci * 16 + kb;
            #pragma unroll
            for (int ot = 0; ot < 8; ot++) {
                unsigned bfr[2];
                bfr[0] = wtu[(ot * 8 + g) * W3S + cg + tig];       // B[k=tig][n=g]
                bfr[1] = wtu[(ot * 8 + g) * W3S + cg + tig + 4];   // B[k=tig+4][n=g]
                mma_tf32(cfr[ot], afr, bfr);
            }
        }
        __syncthreads();           // done reading buffer before refill
    }

    // ---- store: c0=(n=nw+g, o=ot*8+2tig), c1=o+1, c2/c3 = n+8 ----
    float* ob = out + (size_t)b * (OUTo * Tt * Vv) + (size_t)nt * 128;
    #pragma unroll
    for (int ot = 0; ot < 8; ot++) {
        int oA = ot * 8 + 2 * tig, oB = oA + 1;
        float bA = b3s[oA], bB = b3s[oB];
        ob[(size_t)oA * (Tt * Vv) + nw + g]     = cfr[ot][0] + bA;
        ob[(size_t)oB * (Tt * Vv) + nw + g]     = cfr[ot][1] + bB;
        ob[(size_t)oA * (Tt * Vv) + nw + g + 8] = cfr[ot][2] + bA;
        ob[(size_t)oB * (Tt * Vv) + nw + g + 8] = cfr[ot][3] + bB;
    }
}

// ============================================================
extern "C" void kernel_launch(void* const* d_in, const int* in_sizes, int n_in,
                              void* d_out, int out_size) {
    const float* x  = (const float*)d_in[0];
    const float* A  = (const float*)d_in[1];
    const float* W1 = (const float*)d_in[2];
    const float* b1 = (const float*)d_in[3];
    const float* W2 = (const float*)d_in[4];
    const float* b2 = (const float*)d_in[5];
    const float* W4 = (const float*)d_in[6];
    const float* b4 = (const float*)d_in[7];
    const float* W3 = (const float*)d_in[8];
    const float* b3 = (const float*)d_in[9];
    float* out = (float*)d_out;

    k1_xbar<<<Bb * Cc, 128>>>(x);
    k2_rel<<<Bb, 256>>>(W1, b1, W2, b2);
    k3_z<<<Bb * Cc, 128>>>(x, A, W4, b4);
    k4_mma<<<dim3(25, Bb), 256>>>(W3, b3, out);
}